// round 2
// baseline (speedup 1.0000x reference)
#include <cuda_runtime.h>

#define NQ   12
#define DEPTH 4
#define DIM  4096          // 2^12 amplitudes
#define HID  64
#define NPAR (DEPTH*NQ*3)  // 144
#define TPB  256
#define APT  (DIM/TPB)     // 16 amps per thread
#define PPT  (DIM/2/TPB)   // 8 pairs per thread

__global__ __launch_bounds__(TPB)
void qgen_kernel(const float* __restrict__ noise,
                 const float* __restrict__ W1, const float* __restrict__ b1,
                 const float* __restrict__ W2, const float* __restrict__ b2,
                 const float* __restrict__ W3, const float* __restrict__ b3,
                 const float* __restrict__ W4, const float* __restrict__ b4,
                 float* __restrict__ out)
{
    __shared__ float2 psi[DIM];        // 32 KB statevector
    __shared__ float  sh_h[HID];
    __shared__ float  sh_par[NPAR];
    __shared__ float  sh_red[(TPB/32)*NQ];
    __shared__ float  sh_meas[NQ];
    __shared__ float  sh_h2[HID];

    const int row = blockIdx.x;
    const int tid = threadIdx.x;

    // ---- front MLP: h = tanh(noise@W1+b1); params = h@W2+b2 ----
    if (tid < HID) {
        float acc = b1[tid];
        #pragma unroll
        for (int k = 0; k < NQ; k++)
            acc += noise[row*NQ + k] * W1[k*HID + tid];
        sh_h[tid] = tanhf(acc);
    }
    __syncthreads();
    if (tid < NPAR) {
        float acc = b2[tid];
        #pragma unroll
        for (int j = 0; j < HID; j++)
            acc += sh_h[j] * W2[j*NPAR + tid];
        sh_par[tid] = acc;
    }
    // init |0...0>
    #pragma unroll
    for (int k = 0; k < APT; k++) {
        int i = k*TPB + tid;
        psi[i] = make_float2(i == 0 ? 1.0f : 0.0f, 0.0f);
    }
    __syncthreads();

    // ---- circuit: DEPTH layers of 12 fused-U3 gates + CNOT-ring permutation ----
    #pragma unroll 1
    for (int l = 0; l < DEPTH; l++) {
        #pragma unroll
        for (int q = 0; q < NQ; q++) {
            const int bpos = NQ - 1 - q;           // wire q -> bit 11-q
            const int base = (l*NQ + q) * 3;
            float ha = 0.5f * sh_par[base+0];
            float hb = 0.5f * sh_par[base+1];
            float hc = 0.5f * sh_par[base+2];
            float ca, sa, cb, sb, cc, sc;
            __sincosf(ha, &sa, &ca);
            __sincosf(hb, &sb, &cb);
            __sincosf(hc, &sc, &cc);
            // U = RZ(c)RY(b)RX(a); SU(2): u10=-conj(u01), u11=conj(u00)
            float u00r =  cc*cb*ca + sc*sb*sa;
            float u00i =  cc*sb*sa - sc*cb*ca;
            float u01r = -(cc*sb*ca + sc*cb*sa);
            float u01i =  sc*sb*ca - cc*cb*sa;

            const int mlow = (1 << bpos) - 1;
            #pragma unroll
            for (int k = 0; k < PPT; k++) {
                int p  = k*TPB + tid;
                int i0 = ((p >> bpos) << (bpos+1)) | (p & mlow);
                int i1 = i0 | (1 << bpos);
                float2 a0 = psi[i0];
                float2 a1 = psi[i1];
                float b0r =  u00r*a0.x - u00i*a0.y + u01r*a1.x - u01i*a1.y;
                float b0i =  u00r*a0.y + u00i*a0.x + u01r*a1.y + u01i*a1.x;
                float b1r = -u01r*a0.x - u01i*a0.y + u00r*a1.x + u00i*a1.y;
                float b1i = -u01r*a0.y + u01i*a0.x + u00r*a1.y - u00i*a1.x;
                psi[i0] = make_float2(b0r, b0i);
                psi[i1] = make_float2(b1r, b1i);
            }
            __syncthreads();
        }
        // CNOT ring CNOT(0,1)..CNOT(11,0) == GF(2)-linear bit map, one scatter:
        //   y_p = XOR_{j>=p} x_j (p=0..10), y_11 = parity(x_0..x_10)
        float2 r[APT];
        #pragma unroll
        for (int k = 0; k < APT; k++) r[k] = psi[k*TPB + tid];
        __syncthreads();
        #pragma unroll
        for (int k = 0; k < APT; k++) {
            int x  = k*TPB + tid;
            int ys = x;
            ys ^= ys >> 1; ys ^= ys >> 2; ys ^= ys >> 4; ys ^= ys >> 8;
            int y = (ys & 0x7FF) | (((ys ^ (x >> 11)) & 1) << 11);
            psi[y] = r[k];
        }
        __syncthreads();
    }

    // ---- measurement: <Z_q> = sum_i |psi_i|^2 * (1-2*bit_{11-q}(i)) ----
    float z[NQ];
    #pragma unroll
    for (int q = 0; q < NQ; q++) z[q] = 0.0f;
    #pragma unroll
    for (int k = 0; k < APT; k++) {
        int i = k*TPB + tid;
        float2 a = psi[i];
        float p = a.x*a.x + a.y*a.y;
        #pragma unroll
        for (int q = 0; q < NQ; q++)
            z[q] += ((i >> (NQ-1-q)) & 1) ? -p : p;
    }
    #pragma unroll
    for (int q = 0; q < NQ; q++) {
        #pragma unroll
        for (int s = 16; s > 0; s >>= 1)
            z[q] += __shfl_xor_sync(0xffffffffu, z[q], s);
    }
    int warp = tid >> 5, lane = tid & 31;
    if (lane == 0) {
        #pragma unroll
        for (int q = 0; q < NQ; q++) sh_red[warp*NQ + q] = z[q];
    }
    __syncthreads();
    if (tid < NQ) {
        float acc = 0.0f;
        #pragma unroll
        for (int w = 0; w < TPB/32; w++) acc += sh_red[w*NQ + tid];
        sh_meas[tid] = acc;
    }
    __syncthreads();

    // ---- back MLP: out = tanh(meas@W3+b3) @ W4 + b4 ----
    if (tid < HID) {
        float acc = b3[tid];
        #pragma unroll
        for (int k = 0; k < NQ; k++)
            acc += sh_meas[k] * W3[k*HID + tid];
        sh_h2[tid] = tanhf(acc);
    }
    __syncthreads();
    if (tid < 2) {
        float acc = b4[tid];
        #pragma unroll
        for (int j = 0; j < HID; j++)
            acc += sh_h2[j] * W4[j*2 + tid];
        out[row*2 + tid] = acc;
    }
}

extern "C" void kernel_launch(void* const* d_in, const int* in_sizes, int n_in,
                              void* d_out, int out_size)
{
    const float* noise = (const float*)d_in[0];
    const float* W1 = (const float*)d_in[1];
    const float* b1 = (const float*)d_in[2];
    const float* W2 = (const float*)d_in[3];
    const float* b2 = (const float*)d_in[4];
    const float* W3 = (const float*)d_in[5];
    const float* b3 = (const float*)d_in[6];
    const float* W4 = (const float*)d_in[7];
    const float* b4 = (const float*)d_in[8];
    float* out = (float*)d_out;

    int batch = in_sizes[0] / NQ;   // 4096
    qgen_kernel<<<batch, TPB>>>(noise, W1, b1, W2, b2, W3, b3, W4, b4, out);
}

// round 3
// speedup vs baseline: 1.6995x; 1.6995x over previous
#include <cuda_runtime.h>

#define NQ    12
#define DEPTH 4
#define DIM   4096
#define HID   64
#define NPAR  (DEPTH*NQ*3)   // 144
#define TPB   256
#define NG    (DEPTH*NQ)     // 48

__device__ __forceinline__ int swz(int i) { return i ^ ((i >> 4) & 0xF); }

__global__ __launch_bounds__(TPB, 2)
void qgen_kernel(const float* __restrict__ noise,
                 const float* __restrict__ W1, const float* __restrict__ b1,
                 const float* __restrict__ W2, const float* __restrict__ b2,
                 const float* __restrict__ W3, const float* __restrict__ b3,
                 const float* __restrict__ W4, const float* __restrict__ b4,
                 float* __restrict__ out)
{
    __shared__ float2 sv[DIM];          // 32 KB exchange buffer (swizzled)
    __shared__ float  sh_h[HID];
    __shared__ float  sc_s[NPAR], sc_c[NPAR];
    __shared__ float4 gU[NG];           // (u00r, u00i, u01r, u01i) per gate
    __shared__ float  sh_red[(TPB/32)*NQ];
    __shared__ float  sh_meas[NQ];
    __shared__ float  sh_h2[HID];

    const int row  = blockIdx.x;
    const int tid  = threadIdx.x;
    const int lane = tid & 31;
    const int w    = tid >> 5;

    // ---- front MLP: h = tanh(noise@W1+b1) ----
    if (tid < HID) {
        float acc = b1[tid];
        #pragma unroll
        for (int k = 0; k < NQ; k++)
            acc += noise[row*NQ + k] * W1[k*HID + tid];
        sh_h[tid] = tanhf(acc);
    }
    __syncthreads();
    // params = h@W2+b2 ; sincos of half-angles (one per thread, 144 total)
    if (tid < NPAR) {
        float acc = b2[tid];
        #pragma unroll
        for (int j = 0; j < HID; j++)
            acc += sh_h[j] * W2[j*NPAR + tid];
        float s, c;
        __sincosf(0.5f * acc, &s, &c);
        sc_s[tid] = s; sc_c[tid] = c;
    }
    __syncthreads();
    // all 48 gate matrices, once, broadcast via smem
    if (tid < NG) {
        float sa = sc_s[tid*3+0], ca = sc_c[tid*3+0];
        float sb = sc_s[tid*3+1], cb = sc_c[tid*3+1];
        float sg = sc_s[tid*3+2], cg = sc_c[tid*3+2];
        float u00r =  cg*cb*ca + sg*sb*sa;
        float u00i =  cg*sb*sa - sg*cb*ca;
        float u01r = -(cg*sb*ca + sg*cb*sa);
        float u01i =  sg*sb*ca - cg*cb*sa;
        gU[tid] = make_float4(u00r, u00i, u01r, u01i);
    }

    // ---- register-resident statevector: i = w[11:9] | lane[8:4] | k[3:0] ----
    float2 amp[16];
    #pragma unroll
    for (int k = 0; k < 16; k++) amp[k] = make_float2(0.0f, 0.0f);
    if (tid == 0) amp[0].x = 1.0f;
    __syncthreads();

    #pragma unroll 1
    for (int l = 0; l < DEPTH; l++) {
        const int gb = l * NQ;

        // -- gates on local bits 0..3  (qubits 11..8): pure register math --
        #pragma unroll
        for (int b = 0; b < 4; b++) {
            float4 u = gU[gb + (11 - b)];
            #pragma unroll
            for (int m = 0; m < 8; m++) {
                int k0 = ((m >> b) << (b + 1)) | (m & ((1 << b) - 1));
                int k1 = k0 | (1 << b);
                float2 t0 = amp[k0], t1 = amp[k1];
                amp[k0].x =  u.x*t0.x - u.y*t0.y + u.z*t1.x - u.w*t1.y;
                amp[k0].y =  u.x*t0.y + u.y*t0.x + u.z*t1.y + u.w*t1.x;
                amp[k1].x = -u.z*t0.x - u.w*t0.y + u.x*t1.x + u.y*t1.y;
                amp[k1].y = -u.z*t0.y + u.w*t0.x + u.x*t1.y - u.y*t1.x;
            }
        }

        // -- gates on lane bits 4..8 (qubits 7..3): shfl_xor exchange --
        #pragma unroll
        for (int lb = 0; lb < 5; lb++) {
            float4 u = gU[gb + (7 - lb)];
            int side = (lane >> lb) & 1;
            float cmr = u.x;
            float cmi = side ? -u.y : u.y;
            float cor = side ? -u.z : u.z;
            float coi = u.w;
            #pragma unroll
            for (int k = 0; k < 16; k++) {
                float ox = __shfl_xor_sync(0xffffffffu, amp[k].x, 1 << lb);
                float oy = __shfl_xor_sync(0xffffffffu, amp[k].y, 1 << lb);
                float mx = amp[k].x, my = amp[k].y;
                amp[k].x = cmr*mx - cmi*my + cor*ox - coi*oy;
                amp[k].y = cmr*my + cmi*mx + cor*oy + coi*ox;
            }
        }

        // -- transpose L0 -> L1: local' = (i[11:9], i[3]), warp' = i[2:0] --
        #pragma unroll
        for (int k = 0; k < 16; k++)
            sv[swz((w << 9) | (lane << 4) | k)] = amp[k];
        __syncthreads();
        #pragma unroll
        for (int k = 0; k < 16; k++) {
            int i = ((k >> 1) << 9) | (lane << 4) | ((k & 1) << 3) | w;
            amp[k] = sv[swz(i)];
        }
        __syncthreads();

        // -- gates on bits 11..9 (qubits 0..2): now local bits 3..1 of k' --
        #pragma unroll
        for (int b = 1; b < 4; b++) {
            float4 u = gU[gb + (3 - b)];
            #pragma unroll
            for (int m = 0; m < 8; m++) {
                int k0 = ((m >> b) << (b + 1)) | (m & ((1 << b) - 1));
                int k1 = k0 | (1 << b);
                float2 t0 = amp[k0], t1 = amp[k1];
                amp[k0].x =  u.x*t0.x - u.y*t0.y + u.z*t1.x - u.w*t1.y;
                amp[k0].y =  u.x*t0.y + u.y*t0.x + u.z*t1.y + u.w*t1.x;
                amp[k1].x = -u.z*t0.x - u.w*t0.y + u.x*t1.x + u.y*t1.y;
                amp[k1].y = -u.z*t0.y + u.w*t0.x + u.x*t1.y - u.y*t1.x;
            }
        }

        // -- CNOT-ring permutation scatter, fused with transpose back to L0 --
        #pragma unroll
        for (int k = 0; k < 16; k++) {
            int x  = ((k >> 1) << 9) | (lane << 4) | ((k & 1) << 3) | w;
            int ys = x;
            ys ^= ys >> 1; ys ^= ys >> 2; ys ^= ys >> 4; ys ^= ys >> 8;
            int y = (ys & 0x7FF) | (((ys ^ (x >> 11)) & 1) << 11);
            sv[swz(y)] = amp[k];
        }
        __syncthreads();
        #pragma unroll
        for (int k = 0; k < 16; k++)
            amp[k] = sv[swz((w << 9) | (lane << 4) | k)];
        __syncthreads();
    }

    // ---- measurement from registers ----
    // qubits 0..7 -> bits 11..4 (thread-constant sign): z = +/- P_total
    // qubits 8..11 -> bits 3..0 of k: per-bit signed sums
    float P = 0.0f;
    float zb[4] = {0.0f, 0.0f, 0.0f, 0.0f};
    #pragma unroll
    for (int k = 0; k < 16; k++) {
        float pk = amp[k].x*amp[k].x + amp[k].y*amp[k].y;
        P += pk;
        #pragma unroll
        for (int b = 0; b < 4; b++)
            zb[b] += ((k >> b) & 1) ? -pk : pk;
    }
    float z[NQ];
    const int hi = (w << 9) | (lane << 4);
    #pragma unroll
    for (int q = 0; q < 8; q++)
        z[q] = ((hi >> (11 - q)) & 1) ? -P : P;
    #pragma unroll
    for (int q = 8; q < 12; q++)
        z[q] = zb[11 - q];

    #pragma unroll
    for (int q = 0; q < NQ; q++) {
        #pragma unroll
        for (int s = 16; s > 0; s >>= 1)
            z[q] += __shfl_xor_sync(0xffffffffu, z[q], s);
    }
    if (lane == 0) {
        #pragma unroll
        for (int q = 0; q < NQ; q++) sh_red[w*NQ + q] = z[q];
    }
    __syncthreads();
    if (tid < NQ) {
        float acc = 0.0f;
        #pragma unroll
        for (int ww = 0; ww < TPB/32; ww++) acc += sh_red[ww*NQ + tid];
        sh_meas[tid] = acc;
    }
    __syncthreads();

    // ---- back MLP ----
    if (tid < HID) {
        float acc = b3[tid];
        #pragma unroll
        for (int k = 0; k < NQ; k++)
            acc += sh_meas[k] * W3[k*HID + tid];
        sh_h2[tid] = tanhf(acc);
    }
    __syncthreads();
    if (tid < 2) {
        float acc = b4[tid];
        #pragma unroll
        for (int j = 0; j < HID; j++)
            acc += sh_h2[j] * W4[j*2 + tid];
        out[row*2 + tid] = acc;
    }
}

extern "C" void kernel_launch(void* const* d_in, const int* in_sizes, int n_in,
                              void* d_out, int out_size)
{
    const float* noise = (const float*)d_in[0];
    const float* W1 = (const float*)d_in[1];
    const float* b1 = (const float*)d_in[2];
    const float* W2 = (const float*)d_in[3];
    const float* b2 = (const float*)d_in[4];
    const float* W3 = (const float*)d_in[5];
    const float* b3 = (const float*)d_in[6];
    const float* W4 = (const float*)d_in[7];
    const float* b4 = (const float*)d_in[8];
    float* out = (float*)d_out;

    int batch = in_sizes[0] / NQ;   // 4096
    qgen_kernel<<<batch, TPB>>>(noise, W1, b1, W2, b2, W3, b3, W4, b4, out);
}

// round 4
// speedup vs baseline: 1.7003x; 1.0005x over previous
#include <cuda_runtime.h>

#define NQ    12
#define DEPTH 4
#define DIM   4096
#define HID   64
#define NPAR  (DEPTH*NQ*3)   // 144
#define TPB   256
#define NG    (DEPTH*NQ)     // 48

__device__ __forceinline__ int swz(int i) { return i ^ ((i >> 4) & 0xF); }

__global__ __launch_bounds__(TPB, 2)
void qgen_kernel(const float* __restrict__ noise,
                 const float* __restrict__ W1, const float* __restrict__ b1,
                 const float* __restrict__ W2, const float* __restrict__ b2,
                 const float* __restrict__ W3, const float* __restrict__ b3,
                 const float* __restrict__ W4, const float* __restrict__ b4,
                 float* __restrict__ out)
{
    __shared__ float2 sv[DIM];          // 32 KB exchange buffer (swizzled)
    __shared__ float  sh_h[HID];
    __shared__ float  sc_s[NPAR], sc_c[NPAR];
    __shared__ float4 gU[NG];           // (u00r, u00i, u01r, u01i) per gate
    __shared__ float  sh_red[(TPB/32)*NQ];
    __shared__ float  sh_meas[NQ];
    __shared__ float  sh_h2[HID];

    const int row  = blockIdx.x;
    const int tid  = threadIdx.x;
    const int lane = tid & 31;
    const int w    = tid >> 5;

    // ---- front MLP: h = tanh(noise@W1+b1) ----
    if (tid < HID) {
        float acc = b1[tid];
        #pragma unroll
        for (int k = 0; k < NQ; k++)
            acc += noise[row*NQ + k] * W1[k*HID + tid];
        sh_h[tid] = tanhf(acc);
    }
    __syncthreads();
    // params = h@W2+b2 ; sincos of half-angles (one per thread, 144 total)
    if (tid < NPAR) {
        float acc = b2[tid];
        #pragma unroll
        for (int j = 0; j < HID; j++)
            acc += sh_h[j] * W2[j*NPAR + tid];
        float s, c;
        __sincosf(0.5f * acc, &s, &c);
        sc_s[tid] = s; sc_c[tid] = c;
    }
    __syncthreads();
    // all 48 gate matrices, once, broadcast via smem
    if (tid < NG) {
        float sa = sc_s[tid*3+0], ca = sc_c[tid*3+0];
        float sb = sc_s[tid*3+1], cb = sc_c[tid*3+1];
        float sg = sc_s[tid*3+2], cg = sc_c[tid*3+2];
        float u00r =  cg*cb*ca + sg*sb*sa;
        float u00i =  cg*sb*sa - sg*cb*ca;
        float u01r = -(cg*sb*ca + sg*cb*sa);
        float u01i =  sg*sb*ca - cg*cb*sa;
        gU[tid] = make_float4(u00r, u00i, u01r, u01i);
    }

    // ---- register-resident statevector: i = w[11:9] | lane[8:4] | k[3:0] ----
    float2 amp[16];
    #pragma unroll
    for (int k = 0; k < 16; k++) amp[k] = make_float2(0.0f, 0.0f);
    if (tid == 0) amp[0].x = 1.0f;
    __syncthreads();

    #pragma unroll 1
    for (int l = 0; l < DEPTH; l++) {
        const int gb = l * NQ;

        // -- gates on local bits 0..3  (qubits 11..8): pure register math --
        #pragma unroll
        for (int b = 0; b < 4; b++) {
            float4 u = gU[gb + (11 - b)];
            #pragma unroll
            for (int m = 0; m < 8; m++) {
                int k0 = ((m >> b) << (b + 1)) | (m & ((1 << b) - 1));
                int k1 = k0 | (1 << b);
                float2 t0 = amp[k0], t1 = amp[k1];
                amp[k0].x =  u.x*t0.x - u.y*t0.y + u.z*t1.x - u.w*t1.y;
                amp[k0].y =  u.x*t0.y + u.y*t0.x + u.z*t1.y + u.w*t1.x;
                amp[k1].x = -u.z*t0.x - u.w*t0.y + u.x*t1.x + u.y*t1.y;
                amp[k1].y = -u.z*t0.y + u.w*t0.x + u.x*t1.y - u.y*t1.x;
            }
        }

        // -- gates on lane bits 4..8 (qubits 7..3): shfl_xor exchange --
        #pragma unroll
        for (int lb = 0; lb < 5; lb++) {
            float4 u = gU[gb + (7 - lb)];
            int side = (lane >> lb) & 1;
            float cmr = u.x;
            float cmi = side ? -u.y : u.y;
            float cor = side ? -u.z : u.z;
            float coi = u.w;
            #pragma unroll
            for (int k = 0; k < 16; k++) {
                float ox = __shfl_xor_sync(0xffffffffu, amp[k].x, 1 << lb);
                float oy = __shfl_xor_sync(0xffffffffu, amp[k].y, 1 << lb);
                float mx = amp[k].x, my = amp[k].y;
                amp[k].x = cmr*mx - cmi*my + cor*ox - coi*oy;
                amp[k].y = cmr*my + cmi*mx + cor*oy + coi*ox;
            }
        }

        // -- transpose L0 -> L1: local' = (i[11:9], i[3]), warp' = i[2:0] --
        #pragma unroll
        for (int k = 0; k < 16; k++)
            sv[swz((w << 9) | (lane << 4) | k)] = amp[k];
        __syncthreads();
        #pragma unroll
        for (int k = 0; k < 16; k++) {
            int i = ((k >> 1) << 9) | (lane << 4) | ((k & 1) << 3) | w;
            amp[k] = sv[swz(i)];
        }
        __syncthreads();

        // -- gates on bits 11..9 (qubits 0..2): now local bits 3..1 of k' --
        #pragma unroll
        for (int b = 1; b < 4; b++) {
            float4 u = gU[gb + (3 - b)];
            #pragma unroll
            for (int m = 0; m < 8; m++) {
                int k0 = ((m >> b) << (b + 1)) | (m & ((1 << b) - 1));
                int k1 = k0 | (1 << b);
                float2 t0 = amp[k0], t1 = amp[k1];
                amp[k0].x =  u.x*t0.x - u.y*t0.y + u.z*t1.x - u.w*t1.y;
                amp[k0].y =  u.x*t0.y + u.y*t0.x + u.z*t1.y + u.w*t1.x;
                amp[k1].x = -u.z*t0.x - u.w*t0.y + u.x*t1.x + u.y*t1.y;
                amp[k1].y = -u.z*t0.y + u.w*t0.x + u.x*t1.y - u.y*t1.x;
            }
        }

        // -- CNOT-ring permutation scatter, fused with transpose back to L0 --
        #pragma unroll
        for (int k = 0; k < 16; k++) {
            int x  = ((k >> 1) << 9) | (lane << 4) | ((k & 1) << 3) | w;
            int ys = x;
            ys ^= ys >> 1; ys ^= ys >> 2; ys ^= ys >> 4; ys ^= ys >> 8;
            int y = (ys & 0x7FF) | (((ys ^ (x >> 11)) & 1) << 11);
            sv[swz(y)] = amp[k];
        }
        __syncthreads();
        #pragma unroll
        for (int k = 0; k < 16; k++)
            amp[k] = sv[swz((w << 9) | (lane << 4) | k)];
        __syncthreads();
    }

    // ---- measurement from registers ----
    // qubits 0..7 -> bits 11..4 (thread-constant sign): z = +/- P_total
    // qubits 8..11 -> bits 3..0 of k: per-bit signed sums
    float P = 0.0f;
    float zb[4] = {0.0f, 0.0f, 0.0f, 0.0f};
    #pragma unroll
    for (int k = 0; k < 16; k++) {
        float pk = amp[k].x*amp[k].x + amp[k].y*amp[k].y;
        P += pk;
        #pragma unroll
        for (int b = 0; b < 4; b++)
            zb[b] += ((k >> b) & 1) ? -pk : pk;
    }
    float z[NQ];
    const int hi = (w << 9) | (lane << 4);
    #pragma unroll
    for (int q = 0; q < 8; q++)
        z[q] = ((hi >> (11 - q)) & 1) ? -P : P;
    #pragma unroll
    for (int q = 8; q < 12; q++)
        z[q] = zb[11 - q];

    #pragma unroll
    for (int q = 0; q < NQ; q++) {
        #pragma unroll
        for (int s = 16; s > 0; s >>= 1)
            z[q] += __shfl_xor_sync(0xffffffffu, z[q], s);
    }
    if (lane == 0) {
        #pragma unroll
        for (int q = 0; q < NQ; q++) sh_red[w*NQ + q] = z[q];
    }
    __syncthreads();
    if (tid < NQ) {
        float acc = 0.0f;
        #pragma unroll
        for (int ww = 0; ww < TPB/32; ww++) acc += sh_red[ww*NQ + tid];
        sh_meas[tid] = acc;
    }
    __syncthreads();

    // ---- back MLP ----
    if (tid < HID) {
        float acc = b3[tid];
        #pragma unroll
        for (int k = 0; k < NQ; k++)
            acc += sh_meas[k] * W3[k*HID + tid];
        sh_h2[tid] = tanhf(acc);
    }
    __syncthreads();
    if (tid < 2) {
        float acc = b4[tid];
        #pragma unroll
        for (int j = 0; j < HID; j++)
            acc += sh_h2[j] * W4[j*2 + tid];
        out[row*2 + tid] = acc;
    }
}

extern "C" void kernel_launch(void* const* d_in, const int* in_sizes, int n_in,
                              void* d_out, int out_size)
{
    const float* noise = (const float*)d_in[0];
    const float* W1 = (const float*)d_in[1];
    const float* b1 = (const float*)d_in[2];
    const float* W2 = (const float*)d_in[3];
    const float* b2 = (const float*)d_in[4];
    const float* W3 = (const float*)d_in[5];
    const float* b3 = (const float*)d_in[6];
    const float* W4 = (const float*)d_in[7];
    const float* b4 = (const float*)d_in[8];
    float* out = (float*)d_out;

    int batch = in_sizes[0] / NQ;   // 4096
    qgen_kernel<<<batch, TPB>>>(noise, W1, b1, W2, b2, W3, b3, W4, b4, out);
}

// round 6
// speedup vs baseline: 1.8520x; 1.0892x over previous
#include <cuda_runtime.h>

#define NQ    12
#define DEPTH 4
#define DIM   4096
#define HID   64
#define NPAR  (DEPTH*NQ*3)   // 144
#define TPB   256
#define NG    (DEPTH*NQ)     // 48

__device__ __forceinline__ int swz(int i) { return i ^ ((i >> 4) & 0xF); }

__device__ __forceinline__ float2 fma2(float2 a, float2 b, float2 c) {
    float2 d;
    asm("fma.rn.f32x2 %0, %1, %2, %3;"
        : "=l"(reinterpret_cast<unsigned long long&>(d))
        : "l"(reinterpret_cast<unsigned long long&>(a)),
          "l"(reinterpret_cast<unsigned long long&>(b)),
          "l"(reinterpret_cast<unsigned long long&>(c)));
    return d;
}
__device__ __forceinline__ float2 mul2(float2 a, float2 b) {
    float2 d;
    asm("mul.rn.f32x2 %0, %1, %2;"
        : "=l"(reinterpret_cast<unsigned long long&>(d))
        : "l"(reinterpret_cast<unsigned long long&>(a)),
          "l"(reinterpret_cast<unsigned long long&>(b)));
    return d;
}
__device__ __forceinline__ float2 swp(float2 v) { return make_float2(v.y, v.x); }

// pair update: b0 = cd*a0 + cds0*s0 + co0*a1 + cos*s1
//              b1 = co1*a0 + cos*s0 + cd*a1 + cds1*s1
// where sX = swap(aX); coefficient pairs precomputed per gate.

__global__ __launch_bounds__(TPB, 2)
void qgen_kernel(const float* __restrict__ noise,
                 const float* __restrict__ W1, const float* __restrict__ b1,
                 const float* __restrict__ W2, const float* __restrict__ b2,
                 const float* __restrict__ W3, const float* __restrict__ b3,
                 const float* __restrict__ W4, const float* __restrict__ b4,
                 float* __restrict__ out)
{
    __shared__ float2 sv[DIM];          // 32 KB exchange buffer (swizzled)
    __shared__ float  sh_h[HID];
    __shared__ float  sc_s[NPAR], sc_c[NPAR];
    __shared__ float2 gC[NG][6];        // cd, cds0, cds1, co0, co1, cos
    __shared__ float  sh_red[(TPB/32)*NQ];
    __shared__ float  sh_meas[NQ];
    __shared__ float  sh_h2[HID];

    const int row  = blockIdx.x;
    const int tid  = threadIdx.x;
    const int lane = tid & 31;
    const int w    = tid >> 5;

    // ---- front MLP: h = tanh(noise@W1+b1) ----
    if (tid < HID) {
        float acc = b1[tid];
        #pragma unroll
        for (int k = 0; k < NQ; k++)
            acc += noise[row*NQ + k] * W1[k*HID + tid];
        sh_h[tid] = tanhf(acc);
    }
    __syncthreads();
    if (tid < NPAR) {
        float acc = b2[tid];
        #pragma unroll
        for (int j = 0; j < HID; j++)
            acc += sh_h[j] * W2[j*NPAR + tid];
        float s, c;
        __sincosf(0.5f * acc, &s, &c);
        sc_s[tid] = s; sc_c[tid] = c;
    }
    __syncthreads();
    if (tid < NG) {
        float sa = sc_s[tid*3+0], ca = sc_c[tid*3+0];
        float sb = sc_s[tid*3+1], cb = sc_c[tid*3+1];
        float sg = sc_s[tid*3+2], cg = sc_c[tid*3+2];
        float u00r =  cg*cb*ca + sg*sb*sa;
        float u00i =  cg*sb*sa - sg*cb*ca;
        float u01r = -(cg*sb*ca + sg*cb*sa);
        float u01i =  sg*sb*ca - cg*cb*sa;
        gC[tid][0] = make_float2( u00r,  u00r);   // cd
        gC[tid][1] = make_float2(-u00i,  u00i);   // cds0
        gC[tid][2] = make_float2( u00i, -u00i);   // cds1
        gC[tid][3] = make_float2( u01r,  u01r);   // co0
        gC[tid][4] = make_float2(-u01r, -u01r);   // co1
        gC[tid][5] = make_float2(-u01i,  u01i);   // cos
    }

    // ---- phase-1 layout: i = w[11:9] | lane[8:4] | k[3:0] ----
    float2 amp[16];
    #pragma unroll
    for (int k = 0; k < 16; k++) amp[k] = make_float2(0.0f, 0.0f);
    if (tid == 0) amp[0].x = 1.0f;
    __syncthreads();

    #pragma unroll 1
    for (int l = 0; l < DEPTH; l++) {
        const int gb = l * NQ;

        // -- reg gates on local bits 0..3 (qubits 11..8) --
        #pragma unroll
        for (int b = 0; b < 4; b++) {
            const float2 cd   = gC[gb + 11 - b][0];
            const float2 cds0 = gC[gb + 11 - b][1];
            const float2 cds1 = gC[gb + 11 - b][2];
            const float2 co0  = gC[gb + 11 - b][3];
            const float2 co1  = gC[gb + 11 - b][4];
            const float2 cos_ = gC[gb + 11 - b][5];
            #pragma unroll
            for (int m = 0; m < 8; m++) {
                int k0 = ((m >> b) << (b + 1)) | (m & ((1 << b) - 1));
                int k1 = k0 | (1 << b);
                float2 a0 = amp[k0], a1 = amp[k1];
                float2 s0 = swp(a0), s1 = swp(a1);
                amp[k0] = fma2(cd,  a0, fma2(cds0, s0, fma2(co0, a1, mul2(cos_, s1))));
                amp[k1] = fma2(co1, a0, fma2(cos_, s0, fma2(cd,  a1, mul2(cds1, s1))));
            }
        }

        // -- shfl gates on lane bits 4..7 (qubits 7..4) --
        #pragma unroll
        for (int lb = 0; lb < 4; lb++) {
            const int g = gb + 7 - lb;
            const bool side = (lane >> lb) & 1;
            const float2 cd   = gC[g][0];
            const float2 cds  = side ? gC[g][2] : gC[g][1];
            const float2 co   = side ? gC[g][4] : gC[g][3];
            const float2 cos_ = gC[g][5];
            #pragma unroll
            for (int k = 0; k < 16; k++) {
                float2 o;
                o.x = __shfl_xor_sync(0xffffffffu, amp[k].x, 1 << lb);
                o.y = __shfl_xor_sync(0xffffffffu, amp[k].y, 1 << lb);
                float2 m = amp[k];
                float2 sm = swp(m), so = swp(o);
                amp[k] = fma2(cd, m, fma2(cds, sm, fma2(co, o, mul2(cos_, so))));
            }
        }

        // -- transpose to phase-2: k' = i[11:8], lane' = i[7:3], w' = i[2:0] --
        #pragma unroll
        for (int k = 0; k < 16; k++)
            sv[swz((w << 9) | (lane << 4) | k)] = amp[k];
        __syncthreads();
        #pragma unroll
        for (int k = 0; k < 16; k++)
            amp[k] = sv[swz((k << 8) | (lane << 3) | w)];
        __syncthreads();

        // -- reg gates on global bits 8..11 (qubits 3..0): local bits 0..3 --
        #pragma unroll
        for (int b = 0; b < 4; b++) {
            const float2 cd   = gC[gb + 3 - b][0];
            const float2 cds0 = gC[gb + 3 - b][1];
            const float2 cds1 = gC[gb + 3 - b][2];
            const float2 co0  = gC[gb + 3 - b][3];
            const float2 co1  = gC[gb + 3 - b][4];
            const float2 cos_ = gC[gb + 3 - b][5];
            #pragma unroll
            for (int m = 0; m < 8; m++) {
                int k0 = ((m >> b) << (b + 1)) | (m & ((1 << b) - 1));
                int k1 = k0 | (1 << b);
                float2 a0 = amp[k0], a1 = amp[k1];
                float2 s0 = swp(a0), s1 = swp(a1);
                amp[k0] = fma2(cd,  a0, fma2(cds0, s0, fma2(co0, a1, mul2(cos_, s1))));
                amp[k1] = fma2(co1, a0, fma2(cos_, s0, fma2(cd,  a1, mul2(cds1, s1))));
            }
        }

        // -- CNOT-ring permutation scatter, fused with transpose back to L0 --
        #pragma unroll
        for (int k = 0; k < 16; k++) {
            int x  = (k << 8) | (lane << 3) | w;
            int ys = x;
            ys ^= ys >> 1; ys ^= ys >> 2; ys ^= ys >> 4; ys ^= ys >> 8;
            int y = (ys & 0x7FF) | (((ys ^ (x >> 11)) & 1) << 11);
            sv[swz(y)] = amp[k];
        }
        __syncthreads();
        #pragma unroll
        for (int k = 0; k < 16; k++)
            amp[k] = sv[swz((w << 9) | (lane << 4) | k)];
        __syncthreads();
    }

    // ---- measurement from registers (phase-1 layout) ----
    float P = 0.0f;
    float zb[4] = {0.0f, 0.0f, 0.0f, 0.0f};
    #pragma unroll
    for (int k = 0; k < 16; k++) {
        float pk = amp[k].x*amp[k].x + amp[k].y*amp[k].y;
        P += pk;
        #pragma unroll
        for (int b = 0; b < 4; b++)
            zb[b] += ((k >> b) & 1) ? -pk : pk;
    }
    float z[NQ];
    const int hi = (w << 9) | (lane << 4);
    #pragma unroll
    for (int q = 0; q < 8; q++)
        z[q] = ((hi >> (11 - q)) & 1) ? -P : P;
    #pragma unroll
    for (int q = 8; q < 12; q++)
        z[q] = zb[11 - q];

    #pragma unroll
    for (int q = 0; q < NQ; q++) {
        #pragma unroll
        for (int s = 16; s > 0; s >>= 1)
            z[q] += __shfl_xor_sync(0xffffffffu, z[q], s);
    }
    if (lane == 0) {
        #pragma unroll
        for (int q = 0; q < NQ; q++) sh_red[w*NQ + q] = z[q];
    }
    __syncthreads();
    if (tid < NQ) {
        float acc = 0.0f;
        #pragma unroll
        for (int ww = 0; ww < TPB/32; ww++) acc += sh_red[ww*NQ + tid];
        sh_meas[tid] = acc;
    }
    __syncthreads();

    // ---- back MLP ----
    if (tid < HID) {
        float acc = b3[tid];
        #pragma unroll
        for (int k = 0; k < NQ; k++)
            acc += sh_meas[k] * W3[k*HID + tid];
        sh_h2[tid] = tanhf(acc);
    }
    __syncthreads();
    if (tid < 2) {
        float acc = b4[tid];
        #pragma unroll
        for (int j = 0; j < HID; j++)
            acc += sh_h2[j] * W4[j*2 + tid];
        out[row*2 + tid] = acc;
    }
}

extern "C" void kernel_launch(void* const* d_in, const int* in_sizes, int n_in,
                              void* d_out, int out_size)
{
    const float* noise = (const float*)d_in[0];
    const float* W1 = (const float*)d_in[1];
    const float* b1 = (const float*)d_in[2];
    const float* W2 = (const float*)d_in[3];
    const float* b2 = (const float*)d_in[4];
    const float* W3 = (const float*)d_in[5];
    const float* b3 = (const float*)d_in[6];
    const float* W4 = (const float*)d_in[7];
    const float* b4 = (const float*)d_in[8];
    float* out = (float*)d_out;

    int batch = in_sizes[0] / NQ;   // 4096
    qgen_kernel<<<batch, TPB>>>(noise, W1, b1, W2, b2, W3, b3, W4, b4, out);
}